// round 10
// baseline (speedup 1.0000x reference)
#include <cuda_runtime.h>

// CfC recurrent kernel, round 10: R9 cluster design scaled to 512 threads/CTA
// for 4 warps/SMSP of latency hiding. B=256, S=2048, C=64, U=128, H=256.
// 32 clusters x 4 CTAs x 512 threads; cluster owns 8 batch rows end-to-end.
// CTA rank holds W0[:,64r:64r+64) (48KB) + interleaved head quads for units
// [32r,32r+32) (128KB) in SMEM. Per-step exchange of f and h via
// st.shared::cluster + 2 cluster barriers. Packed fp32x2 FMA, row-pair lanes.

typedef unsigned long long u64;

#define S_LEN 2048
#define NTHRD 512

// SMEM layout (u64 units)
#define OW0   0                 // float[192][64]  = 6144 u64 (48KB)
#define OWH   6144              // float[256][128] = 16384 u64 (128KB)
#define OFEAT 22528             // u64 feat2[192][4]  (x|h as (row0,row1) pairs)
#define OFSM  23296             // u64 fsm2[256][4]   (backbone f pairs)
#define ORED  24320             // u64 red[4096]      (red1[16][4][64] / red2[8][4][128])
#define OTOT  28416
#define SMEM_BYTES (OTOT * 8)   // 227328

__device__ __forceinline__ u64 pack2(float lo, float hi) {
    u64 r;
    asm("mov.b64 %0, {%1, %2};"
        : "=l"(r) : "r"(__float_as_uint(lo)), "r"(__float_as_uint(hi)));
    return r;
}
__device__ __forceinline__ void fma2(u64& d, u64 a, u64 b) {
    asm("fma.rn.f32x2 %0, %1, %2, %0;" : "+l"(d) : "l"(a), "l"(b));
}
__device__ __forceinline__ u64 add2(u64 a, u64 b) {
    u64 r;
    asm("add.rn.f32x2 %0, %1, %2;" : "=l"(r) : "l"(a), "l"(b));
    return r;
}
__device__ __forceinline__ float2 unpk(u64 v) {
    unsigned lo, hi;
    asm("mov.b64 {%0, %1}, %2;" : "=r"(lo), "=r"(hi) : "l"(v));
    return make_float2(__uint_as_float(lo), __uint_as_float(hi));
}
__device__ __forceinline__ unsigned smem_u32(const void* p) {
    unsigned a;
    asm("{ .reg .u64 t; cvta.to.shared.u64 t, %1; cvt.u32.u64 %0, t; }"
        : "=r"(a) : "l"(p));
    return a;
}
__device__ __forceinline__ unsigned mapa_rank(unsigned addr, unsigned rank) {
    unsigned r;
    asm("mapa.shared::cluster.u32 %0, %1, %2;" : "=r"(r) : "r"(addr), "r"(rank));
    return r;
}
__device__ __forceinline__ void st_cluster(unsigned addr, u64 v) {
    asm volatile("st.shared::cluster.b64 [%0], %1;" :: "r"(addr), "l"(v) : "memory");
}
__device__ __forceinline__ unsigned ctarank() {
    unsigned r;
    asm("mov.u32 %0, %%cluster_ctarank;" : "=r"(r));
    return r;
}
#define CLUSTER_BAR() do { \
    asm volatile("barrier.cluster.arrive.aligned;" ::: "memory"); \
    asm volatile("barrier.cluster.wait.aligned;"   ::: "memory"); \
} while (0)

__global__ void __launch_bounds__(NTHRD, 1) __cluster_dims__(4, 1, 1)
cfc_kernel(
    const float* __restrict__ x_codes,   // [B,S,64]
    const float* __restrict__ h0,        // [B,128]
    const float* __restrict__ tsp,       // [B,S]
    const float* __restrict__ W0,        // [192,256]
    const float* __restrict__ b0,        // [256]
    const float* __restrict__ W1, const float* __restrict__ b1,  // [256,128]
    const float* __restrict__ W2, const float* __restrict__ b2,
    const float* __restrict__ Wa, const float* __restrict__ ba,
    const float* __restrict__ Wb, const float* __restrict__ bb,
    float* __restrict__ out)             // [B,S,128]
{
    extern __shared__ u64 smu[];
    float* sW0  = (float*)(smu + OW0);
    float* sWH  = (float*)(smu + OWH);
    u64* feat2  = smu + OFEAT;
    u64* fsm2   = smu + OFSM;
    u64* red    = smu + ORED;

    const int tid = threadIdx.x;
    const unsigned rank = ctarank();
    const int brow = (blockIdx.x >> 2) * 8;

    // ---- one-time: W0 slice [192][64] ----
    for (int idx = tid; idx < 192 * 16; idx += NTHRD) {     // float4 units
        int k = idx >> 4, q = idx & 15;
        float4 v = *(const float4*)(W0 + (size_t)k * 256 + rank * 64 + q * 4);
        ((float4*)sW0)[idx] = v;
    }
    // ---- one-time: head slice interleaved sWH[k][4j+h] = Wh[k][32*rank+j] ----
    for (int idx = tid; idx < 256 * 128; idx += NTHRD) {
        int k = idx >> 7, c = idx & 127, j = c >> 2, h = c & 3;
        const float* src = (h == 0 ? W1 : h == 1 ? W2 : h == 2 ? Wa : Wb);
        sWH[idx] = src[(size_t)k * 128 + 32 * rank + j];
    }
    // ---- one-time: h0 into feat2[64+u][rp] ----
    {
        int u = tid & 127, rp = tid >> 7;
        float a = h0[(size_t)(brow + 2 * rp) * 128 + u];
        float c = h0[(size_t)(brow + 2 * rp + 1) * 128 + u];
        feat2[(64 + u) * 4 + rp] = pack2(a, c);
    }

    // ---- role constants ----
    // GEMM1: 32 col-groups (2 cols) x 16 k-groups (12 k)
    const int cg  = tid & 31;
    const int k1b = (tid >> 5) * 12;
    // reduce1 (tid<256): 64 cols x 4 row-pairs
    const int col1 = tid & 63;
    const int rp1  = tid >> 6;       // valid for tid<256
    const int gc1  = 64 * (int)rank + col1;
    const u64 b0d  = pack2(b0[gc1], b0[gc1]);
    // x writer (tid>=256): 64 ch x 4 rp
    const int xt  = tid & 255;
    const int ch  = xt & 63;
    const int rpx = xt >> 6;
    const float* xa = x_codes + (size_t)(brow + 2 * rpx) * S_LEN * 64 + ch;
    const float* xb = x_codes + (size_t)(brow + 2 * rpx + 1) * S_LEN * 64 + ch;
    // GEMM2: 64 col-groups (2 cols) x 8 k-groups (32 k)
    const int cg2 = tid & 63;
    const int k2b = (tid >> 6) * 32;
    const float* wp2c = sWH + k2b * 128 + 2 * cg2;
    const u64* fp2c = fsm2 + k2b * 4;
    // gate (tid<128): 32 units x 4 row-pairs
    const int jg  = tid & 31;
    const int rpg = (tid >> 5) & 3;
    const int ug  = 32 * (int)rank + jg;
    const u64 b1d = pack2(b1[ug], b1[ug]);
    const u64 b2d = pack2(b2[ug], b2[ug]);
    const u64 bad = pack2(ba[ug], ba[ug]);
    const u64 bbd = pack2(bb[ug], bb[ug]);
    const int gr0 = brow + 2 * rpg;
    const float* tsa = tsp + (size_t)gr0 * S_LEN;
    const float* tsb = tsp + (size_t)(gr0 + 1) * S_LEN;
    float* outa = out + (size_t)gr0 * S_LEN * 128 + ug;
    float* outb = out + (size_t)(gr0 + 1) * S_LEN * 128 + ug;

    // x(0) write + x(1) prefetch (tid>=256 owns x thereafter; here all help)
    float xr0 = 0.f, xr1 = 0.f;
    if (tid >= 256) {
        float v0 = xa[0], v1 = xb[0];
        feat2[ch * 4 + rpx] = pack2((v0 - 65.0f) * 0.01f, (v1 - 65.0f) * 0.01f);
        xr0 = xa[64]; xr1 = xb[64];
    }
    __syncthreads();
    CLUSTER_BAR();

    // ---- DSMEM base addresses ----
    unsigned fsm_base[4], feat_base[4];
    {
        unsigned lf = smem_u32(fsm2), lh = smem_u32(feat2);
        #pragma unroll
        for (int r = 0; r < 4; ++r) {
            fsm_base[r]  = mapa_rank(lf, (unsigned)r);
            feat_base[r] = mapa_rank(lh, (unsigned)r);
        }
    }

    for (int s = 0; s < S_LEN; ++s) {
        // ts prefetch for gate (long-latency, consumed at step end)
        float tsv0 = 0.f, tsv1 = 0.f;
        if (tid < 128) { tsv0 = tsa[s]; tsv1 = tsb[s]; }

        // ---- GEMM1 partials: 2 cols x 8 rows over 12 k ----
        u64 a00 = 0, a01 = 0, a02 = 0, a03 = 0;
        u64 a10 = 0, a11 = 0, a12 = 0, a13 = 0;
        {
            const float* wp = sW0 + k1b * 64 + 2 * cg;
            const u64* fp = feat2 + k1b * 4;
            #pragma unroll 12
            for (int k = 0; k < 12; ++k) {
                float2 w = *(const float2*)(wp + k * 64);
                u64 w0d = pack2(w.x, w.x), w1d = pack2(w.y, w.y);
                ulonglong2 f01 = *(const ulonglong2*)(fp + k * 4);
                ulonglong2 f23 = *(const ulonglong2*)(fp + k * 4 + 2);
                fma2(a00, f01.x, w0d); fma2(a01, f01.y, w0d);
                fma2(a02, f23.x, w0d); fma2(a03, f23.y, w0d);
                fma2(a10, f01.x, w1d); fma2(a11, f01.y, w1d);
                fma2(a12, f23.x, w1d); fma2(a13, f23.y, w1d);
            }
        }
        {   // red1 layout [ks(16)][rp(4)][col(64)]
            u64* rb = red + (tid >> 5) * 256 + 2 * cg;
            *(ulonglong2*)(rb)       = make_ulonglong2(a00, a10);
            *(ulonglong2*)(rb + 64)  = make_ulonglong2(a01, a11);
            *(ulonglong2*)(rb + 128) = make_ulonglong2(a02, a12);
            *(ulonglong2*)(rb + 192) = make_ulonglong2(a03, a13);
        }
        __syncthreads();  // S2: red1 ready; GEMM1 feat reads complete

        if (tid < 256) {
            // ---- reduce1 (16 partials) + lecun_tanh + f-push x4 CTAs ----
            const u64* rr = red + rp1 * 64 + col1;
            u64 ssum = rr[0];
            #pragma unroll
            for (int q = 1; q < 16; ++q) ssum = add2(ssum, rr[q * 256]);
            ssum = add2(ssum, b0d);
            float2 v = unpk(ssum);
            float t0 = 1.7159f * tanhf(0.666f * v.x);
            float t1 = 1.7159f * tanhf(0.666f * v.y);
            u64 fv = pack2(t0, t1);
            unsigned off = (unsigned)((gc1 * 4 + rp1) * 8);
            #pragma unroll
            for (int r = 0; r < 4; ++r) st_cluster(fsm_base[r] + off, fv);
        } else {
            // ---- write x(s+1) into feat2 (safe: GEMM1 reads done at S2),
            //      prefetch x(s+2) ----
            if (s + 1 < S_LEN) {
                feat2[ch * 4 + rpx] =
                    pack2((xr0 - 65.0f) * 0.01f, (xr1 - 65.0f) * 0.01f);
                if (s + 2 < S_LEN) {
                    xr0 = xa[(size_t)(s + 2) * 64];
                    xr1 = xb[(size_t)(s + 2) * 64];
                }
            }
        }
        CLUSTER_BAR();  // BAR_A: all f slices delivered everywhere

        // ---- GEMM2 partials: 2 cols x 8 rows over 32 k ----
        u64 q00 = 0, q01 = 0, q02 = 0, q03 = 0;
        u64 q10 = 0, q11 = 0, q12 = 0, q13 = 0;
        #pragma unroll 8
        for (int k = 0; k < 32; ++k) {
            float2 w = *(const float2*)(wp2c + k * 128);
            u64 w0d = pack2(w.x, w.x), w1d = pack2(w.y, w.y);
            ulonglong2 f01 = *(const ulonglong2*)(fp2c + k * 4);
            ulonglong2 f23 = *(const ulonglong2*)(fp2c + k * 4 + 2);
            fma2(q00, f01.x, w0d); fma2(q01, f01.y, w0d);
            fma2(q02, f23.x, w0d); fma2(q03, f23.y, w0d);
            fma2(q10, f01.x, w1d); fma2(q11, f01.y, w1d);
            fma2(q12, f23.x, w1d); fma2(q13, f23.y, w1d);
        }
        {   // red2 layout [ks2(8)][rp(4)][col(128)] (aliases red1; BAR_A ordered)
            u64* rb = red + (tid >> 6) * 512 + 2 * cg2;
            *(ulonglong2*)(rb)       = make_ulonglong2(q00, q10);
            *(ulonglong2*)(rb + 128) = make_ulonglong2(q01, q11);
            *(ulonglong2*)(rb + 256) = make_ulonglong2(q02, q12);
            *(ulonglong2*)(rb + 384) = make_ulonglong2(q03, q13);
        }
        __syncthreads();  // S3: red2 ready

        // ---- gate: reduce 8 k-partials, sigmoid blend, out + h-push ----
        if (tid < 128) {
            const u64* rr = red + rpg * 128 + 4 * jg;
            ulonglong2 g0 = *(const ulonglong2*)(rr);       // (ff1, ff2) partial
            ulonglong2 g1 = *(const ulonglong2*)(rr + 2);   // (ta,  tb ) partial
            u64 p1 = g0.x, p2 = g0.y, pa = g1.x, pb = g1.y;
            #pragma unroll
            for (int q = 1; q < 8; ++q) {
                ulonglong2 h0v = *(const ulonglong2*)(rr + q * 512);
                ulonglong2 h1v = *(const ulonglong2*)(rr + q * 512 + 2);
                p1 = add2(p1, h0v.x); p2 = add2(p2, h0v.y);
                pa = add2(pa, h1v.x); pb = add2(pb, h1v.y);
            }
            p1 = add2(p1, b1d); p2 = add2(p2, b2d);
            pa = add2(pa, bad); pb = add2(pb, bbd);
            float2 f1v = unpk(p1), f2v = unpk(p2), av = unpk(pa), bv = unpk(pb);
            float z0 = bv.x - av.x * tsv0;
            float z1 = bv.y - av.y * tsv1;
            float ti0 = 1.0f / (1.0f + expf(-z0));
            float ti1 = 1.0f / (1.0f + expf(-z1));
            float nh0 = f1v.x + ti0 * (f2v.x - f1v.x);
            float nh1 = f1v.y + ti1 * (f2v.y - f1v.y);
            outa[(size_t)s * 128] = nh0;
            outb[(size_t)s * 128] = nh1;
            u64 hv = pack2(nh0, nh1);
            unsigned off = (unsigned)(((64 + ug) * 4 + rpg) * 8);
            #pragma unroll
            for (int r = 0; r < 4; ++r) st_cluster(feat_base[r] + off, hv);
        }
        CLUSTER_BAR();  // BAR_B: h (and x(s+1)) visible; next step may start
    }
}

extern "C" void kernel_launch(void* const* d_in, const int* in_sizes, int n_in,
                              void* d_out, int out_size) {
    const float* x_codes = (const float*)d_in[0];
    const float* h0      = (const float*)d_in[1];
    const float* tsp     = (const float*)d_in[2];
    const float* W0      = (const float*)d_in[3];
    const float* b0      = (const float*)d_in[4];
    const float* W1      = (const float*)d_in[5];
    const float* b1      = (const float*)d_in[6];
    const float* W2      = (const float*)d_in[7];
    const float* b2      = (const float*)d_in[8];
    const float* Wa      = (const float*)d_in[9];
    const float* ba      = (const float*)d_in[10];
    const float* Wb      = (const float*)d_in[11];
    const float* bb      = (const float*)d_in[12];
    float* out = (float*)d_out;

    cudaFuncSetAttribute(cfc_kernel,
                         cudaFuncAttributeMaxDynamicSharedMemorySize, SMEM_BYTES);

    cfc_kernel<<<128, NTHRD, SMEM_BYTES>>>(
        x_codes, h0, tsp, W0, b0, W1, b1, W2, b2, Wa, ba, Wb, bb, out);
}

// round 11
// speedup vs baseline: 1.1749x; 1.1749x over previous
#include <cuda_runtime.h>

// CfC recurrent kernel, round 11: R9 cluster design (256 thr/CTA, weights
// SMEM-resident in a 4-CTA cluster) + GEMM2 weights pinned in REGISTERS
// (48 of 64 k-slices per thread; 16 remain in SMEM) to remove ~75% of the
// per-step weight crossbar traffic. B=256, S=2048, C=64, U=128, H=256.
// 32 clusters x 4 CTAs x 256 threads; cluster owns 8 batch rows end-to-end.
// Per-step f/h exchange via st.shared::cluster + 2 cluster barriers.
// All math packed fp32x2 FMA, row-pair lanes.

typedef unsigned long long u64;

#define S_LEN 2048
#define NTHRD 256
#define KREG 48                 // GEMM2 k-slices held in registers per thread

// SMEM layout (u64 units)
#define OW0   0                 // float[192][64]  = 6144 u64 (48KB)
#define OWH   6144              // float[256][128] = 16384 u64 (128KB)
#define OFEAT 22528             // u64 feat2[192][4]  (x|h as (row0,row1) pairs)
#define OFSM  23296             // u64 fsm2[256][4]   (backbone f pairs)
#define ORED  24320             // u64 red[2048]      (red1/red2 aliased)
#define OTOT  26368
#define SMEM_BYTES (OTOT * 8)   // 210944

__device__ __forceinline__ u64 pack2(float lo, float hi) {
    u64 r;
    asm("mov.b64 %0, {%1, %2};"
        : "=l"(r) : "r"(__float_as_uint(lo)), "r"(__float_as_uint(hi)));
    return r;
}
__device__ __forceinline__ void fma2(u64& d, u64 a, u64 b) {
    asm("fma.rn.f32x2 %0, %1, %2, %0;" : "+l"(d) : "l"(a), "l"(b));
}
__device__ __forceinline__ u64 add2(u64 a, u64 b) {
    u64 r;
    asm("add.rn.f32x2 %0, %1, %2;" : "=l"(r) : "l"(a), "l"(b));
    return r;
}
__device__ __forceinline__ float2 unpk(u64 v) {
    unsigned lo, hi;
    asm("mov.b64 {%0, %1}, %2;" : "=r"(lo), "=r"(hi) : "l"(v));
    return make_float2(__uint_as_float(lo), __uint_as_float(hi));
}
__device__ __forceinline__ unsigned smem_u32(const void* p) {
    unsigned a;
    asm("{ .reg .u64 t; cvta.to.shared.u64 t, %1; cvt.u32.u64 %0, t; }"
        : "=r"(a) : "l"(p));
    return a;
}
__device__ __forceinline__ unsigned mapa_rank(unsigned addr, unsigned rank) {
    unsigned r;
    asm("mapa.shared::cluster.u32 %0, %1, %2;" : "=r"(r) : "r"(addr), "r"(rank));
    return r;
}
__device__ __forceinline__ void st_cluster(unsigned addr, u64 v) {
    asm volatile("st.shared::cluster.b64 [%0], %1;" :: "r"(addr), "l"(v) : "memory");
}
__device__ __forceinline__ unsigned ctarank() {
    unsigned r;
    asm("mov.u32 %0, %%cluster_ctarank;" : "=r"(r));
    return r;
}
#define CLUSTER_BAR() do { \
    asm volatile("barrier.cluster.arrive.aligned;" ::: "memory"); \
    asm volatile("barrier.cluster.wait.aligned;"   ::: "memory"); \
} while (0)

__global__ void __launch_bounds__(NTHRD, 1) __cluster_dims__(4, 1, 1)
cfc_kernel(
    const float* __restrict__ x_codes,   // [B,S,64]
    const float* __restrict__ h0,        // [B,128]
    const float* __restrict__ tsp,       // [B,S]
    const float* __restrict__ W0,        // [192,256]
    const float* __restrict__ b0,        // [256]
    const float* __restrict__ W1, const float* __restrict__ b1,  // [256,128]
    const float* __restrict__ W2, const float* __restrict__ b2,
    const float* __restrict__ Wa, const float* __restrict__ ba,
    const float* __restrict__ Wb, const float* __restrict__ bb,
    float* __restrict__ out)             // [B,S,128]
{
    extern __shared__ u64 smu[];
    float* sW0  = (float*)(smu + OW0);
    float* sWH  = (float*)(smu + OWH);
    u64* feat2  = smu + OFEAT;
    u64* fsm2   = smu + OFSM;
    u64* red    = smu + ORED;

    const int tid = threadIdx.x;
    const unsigned rank = ctarank();
    const int brow = (blockIdx.x >> 2) * 8;

    // ---- one-time: load W0 slice [192][64] (cols 64*rank..) ----
    for (int idx = tid; idx < 192 * 16; idx += NTHRD) {     // float4 units
        int k = idx >> 4, q = idx & 15;
        float4 v = *(const float4*)(W0 + (size_t)k * 256 + rank * 64 + q * 4);
        ((float4*)sW0)[idx] = v;
    }
    // ---- one-time: head slice interleaved sWH[k][4j+h] = Wh[k][32*rank+j] ----
    for (int idx = tid; idx < 256 * 128; idx += NTHRD) {
        int k = idx >> 7, c = idx & 127, j = c >> 2, h = c & 3;
        const float* src = (h == 0 ? W1 : h == 1 ? W2 : h == 2 ? Wa : Wb);
        sWH[idx] = src[(size_t)k * 128 + 32 * rank + j];
    }
    // ---- one-time: h0 into feat2[64+u][rp] as (row2rp, row2rp+1) ----
    for (int idx = tid; idx < 512; idx += NTHRD) {
        int u = idx & 127, rp = idx >> 7;
        float a = h0[(size_t)(brow + 2 * rp) * 128 + u];
        float c = h0[(size_t)(brow + 2 * rp + 1) * 128 + u];
        feat2[(64 + u) * 4 + rp] = pack2(a, c);
    }
    __syncthreads();
    CLUSTER_BAR();

    // ---- DSMEM base addresses (once) ----
    unsigned fsm_base[4], feat_base[4];
    {
        unsigned lf = smem_u32(fsm2), lh = smem_u32(feat2);
        #pragma unroll
        for (int r = 0; r < 4; ++r) {
            fsm_base[r]  = mapa_rank(lf, (unsigned)r);
            feat_base[r] = mapa_rank(lh, (unsigned)r);
        }
    }

    // ---- per-thread role constants ----
    // GEMM1: 32 col-groups (2 cols) x 8 k-groups (24 k)
    const int cg  = tid & 31;
    const int k1b = (tid >> 5) * 24;
    // reduce1 / f-push: 64 cols x 4 row-pairs
    const int col1 = tid & 63;
    const int rp1  = tid >> 6;
    const int gc1  = 64 * (int)rank + col1;
    const u64 b0d  = pack2(b0[gc1], b0[gc1]);
    // GEMM2: 64 col-groups (2 of 128 local cols) x 4 k-groups (64 k)
    const int cg2 = tid & 63;
    const int k2b = (tid >> 6) * 64;
    const float* wp2c = sWH + k2b * 128 + 2 * cg2;
    const u64* fp2c = fsm2 + k2b * 4;
    // gate: 32 units x 4 row-pairs (threads 0..127)
    const int jg  = tid & 31;
    const int rpg = (tid >> 5) & 3;
    const int ug  = 32 * (int)rank + jg;
    const u64 b1d = pack2(b1[ug], b1[ug]);
    const u64 b2d = pack2(b2[ug], b2[ug]);
    const u64 bad = pack2(ba[ug], ba[ug]);
    const u64 bbd = pack2(bb[ug], bb[ug]);
    const int gr0 = brow + 2 * rpg;
    const float* tsa = tsp + (size_t)gr0 * S_LEN;
    const float* tsb = tsp + (size_t)(gr0 + 1) * S_LEN;
    float* outa = out + (size_t)gr0 * S_LEN * 128 + ug;
    float* outb = out + (size_t)(gr0 + 1) * S_LEN * 128 + ug;
    // x loader: 64 channels x 4 row-pairs
    const int ch  = tid & 63;
    const int rpx = tid >> 6;
    const float* xa = x_codes + (size_t)(brow + 2 * rpx) * S_LEN * 64 + ch;
    const float* xb = x_codes + (size_t)(brow + 2 * rpx + 1) * S_LEN * 64 + ch;

    // ---- pin first KREG GEMM2 weight k-slices in registers ----
    float2 wreg[KREG];
    #pragma unroll
    for (int k = 0; k < KREG; ++k)
        wreg[k] = *(const float2*)(wp2c + k * 128);

    float xr0 = xa[0], xr1 = xb[0];

    for (int s = 0; s < S_LEN; ++s) {
        // ts prefetch for gate (used far below)
        float tsv0 = 0.f, tsv1 = 0.f;
        if (tid < 128) { tsv0 = tsa[s]; tsv1 = tsb[s]; }

        // write x(s) (scaled) into feat2[0..63]
        feat2[ch * 4 + rpx] = pack2((xr0 - 65.0f) * 0.01f, (xr1 - 65.0f) * 0.01f);
        __syncthreads();  // S1: feat ready (x local, h via BAR_B of prev step)

        // ---- GEMM1 partials: 2 cols x 8 rows over 24 k ----
        u64 a00 = 0, a01 = 0, a02 = 0, a03 = 0;
        u64 a10 = 0, a11 = 0, a12 = 0, a13 = 0;
        {
            const float* wp = sW0 + k1b * 64 + 2 * cg;
            const u64* fp = feat2 + k1b * 4;
            #pragma unroll 12
            for (int k = 0; k < 24; ++k) {
                float2 w = *(const float2*)(wp + k * 64);
                u64 w0d = pack2(w.x, w.x), w1d = pack2(w.y, w.y);
                ulonglong2 f01 = *(const ulonglong2*)(fp + k * 4);
                ulonglong2 f23 = *(const ulonglong2*)(fp + k * 4 + 2);
                fma2(a00, f01.x, w0d); fma2(a01, f01.y, w0d);
                fma2(a02, f23.x, w0d); fma2(a03, f23.y, w0d);
                fma2(a10, f01.x, w1d); fma2(a11, f01.y, w1d);
                fma2(a12, f23.x, w1d); fma2(a13, f23.y, w1d);
            }
        }
        {   // red1 layout [ks(8)][rp(4)][col(64)]
            u64* rb = red + (tid >> 5) * 256 + 2 * cg;
            *(ulonglong2*)(rb)       = make_ulonglong2(a00, a10);
            *(ulonglong2*)(rb + 64)  = make_ulonglong2(a01, a11);
            *(ulonglong2*)(rb + 128) = make_ulonglong2(a02, a12);
            *(ulonglong2*)(rb + 192) = make_ulonglong2(a03, a13);
        }
        __syncthreads();  // S2: red1 ready

        // ---- reduce1 + lecun_tanh + push f slice to all 4 CTAs ----
        {
            const u64* rr = red + rp1 * 64 + col1;
            u64 ssum = rr[0];
            #pragma unroll
            for (int q = 1; q < 8; ++q) ssum = add2(ssum, rr[q * 256]);
            ssum = add2(ssum, b0d);
            float2 v = unpk(ssum);
            float t0 = 1.7159f * tanhf(0.666f * v.x);
            float t1 = 1.7159f * tanhf(0.666f * v.y);
            u64 fv = pack2(t0, t1);
            unsigned off = (unsigned)((gc1 * 4 + rp1) * 8);
            #pragma unroll
            for (int r = 0; r < 4; ++r) st_cluster(fsm_base[r] + off, fv);
        }
        // prefetch x(s+1) while waiting
        if (s + 1 < S_LEN) { xr0 = xa[(size_t)(s + 1) * 64]; xr1 = xb[(size_t)(s + 1) * 64]; }
        CLUSTER_BAR();  // BAR_A: all f slices delivered everywhere

        // ---- GEMM2 partials: 2 local cols x 8 rows over 64 k ----
        // First KREG k's use register-resident weights (no LDS for weights);
        // remaining k's stream weights from SMEM.
        u64 q00 = 0, q01 = 0, q02 = 0, q03 = 0;
        u64 q10 = 0, q11 = 0, q12 = 0, q13 = 0;
        #pragma unroll
        for (int k = 0; k < KREG; ++k) {
            float2 w = wreg[k];
            u64 w0d = pack2(w.x, w.x), w1d = pack2(w.y, w.y);
            ulonglong2 f01 = *(const ulonglong2*)(fp2c + k * 4);
            ulonglong2 f23 = *(const ulonglong2*)(fp2c + k * 4 + 2);
            fma2(q00, f01.x, w0d); fma2(q01, f01.y, w0d);
            fma2(q02, f23.x, w0d); fma2(q03, f23.y, w0d);
            fma2(q10, f01.x, w1d); fma2(q11, f01.y, w1d);
            fma2(q12, f23.x, w1d); fma2(q13, f23.y, w1d);
        }
        #pragma unroll 8
        for (int k = KREG; k < 64; ++k) {
            float2 w = *(const float2*)(wp2c + k * 128);
            u64 w0d = pack2(w.x, w.x), w1d = pack2(w.y, w.y);
            ulonglong2 f01 = *(const ulonglong2*)(fp2c + k * 4);
            ulonglong2 f23 = *(const ulonglong2*)(fp2c + k * 4 + 2);
            fma2(q00, f01.x, w0d); fma2(q01, f01.y, w0d);
            fma2(q02, f23.x, w0d); fma2(q03, f23.y, w0d);
            fma2(q10, f01.x, w1d); fma2(q11, f01.y, w1d);
            fma2(q12, f23.x, w1d); fma2(q13, f23.y, w1d);
        }
        {   // red2 layout [ks2(4)][rp(4)][col(128)] (aliases red1 — safe: BAR_A ordered)
            u64* rb = red + (tid >> 6) * 512 + 2 * cg2;
            *(ulonglong2*)(rb)       = make_ulonglong2(q00, q10);
            *(ulonglong2*)(rb + 128) = make_ulonglong2(q01, q11);
            *(ulonglong2*)(rb + 256) = make_ulonglong2(q02, q12);
            *(ulonglong2*)(rb + 384) = make_ulonglong2(q03, q13);
        }
        __syncthreads();  // S3: red2 ready

        // ---- gate: reduce 4 k-partials, sigmoid blend, out + h-push ----
        if (tid < 128) {
            const u64* rr = red + rpg * 128 + 4 * jg;
            ulonglong2 g0 = *(const ulonglong2*)(rr);       // (ff1, ff2) partial
            ulonglong2 g1 = *(const ulonglong2*)(rr + 2);   // (ta,  tb ) partial
            u64 p1 = g0.x, p2 = g0.y, pa = g1.x, pb = g1.y;
            #pragma unroll
            for (int q = 1; q < 4; ++q) {
                ulonglong2 h0v = *(const ulonglong2*)(rr + q * 512);
                ulonglong2 h1v = *(const ulonglong2*)(rr + q * 512 + 2);
                p1 = add2(p1, h0v.x); p2 = add2(p2, h0v.y);
                pa = add2(pa, h1v.x); pb = add2(pb, h1v.y);
            }
            p1 = add2(p1, b1d); p2 = add2(p2, b2d);
            pa = add2(pa, bad); pb = add2(pb, bbd);
            float2 f1v = unpk(p1), f2v = unpk(p2), av = unpk(pa), bv = unpk(pb);
            float z0 = bv.x - av.x * tsv0;
            float z1 = bv.y - av.y * tsv1;
            float ti0 = 1.0f / (1.0f + expf(-z0));
            float ti1 = 1.0f / (1.0f + expf(-z1));
            float nh0 = f1v.x + ti0 * (f2v.x - f1v.x);
            float nh1 = f1v.y + ti1 * (f2v.y - f1v.y);
            outa[(size_t)s * 128] = nh0;
            outb[(size_t)s * 128] = nh1;
            u64 hv = pack2(nh0, nh1);
            unsigned off = (unsigned)(((64 + ug) * 4 + rpg) * 8);
            #pragma unroll
            for (int r = 0; r < 4; ++r) st_cluster(feat_base[r] + off, hv);
        }
        CLUSTER_BAR();  // BAR_B: h delivered everywhere; safe to start next step
    }
}

extern "C" void kernel_launch(void* const* d_in, const int* in_sizes, int n_in,
                              void* d_out, int out_size) {
    const float* x_codes = (const float*)d_in[0];
    const float* h0      = (const float*)d_in[1];
    const float* tsp     = (const float*)d_in[2];
    const float* W0      = (const float*)d_in[3];
    const float* b0      = (const float*)d_in[4];
    const float* W1      = (const float*)d_in[5];
    const float* b1      = (const float*)d_in[6];
    const float* W2      = (const float*)d_in[7];
    const float* b2      = (const float*)d_in[8];
    const float* Wa      = (const float*)d_in[9];
    const float* ba      = (const float*)d_in[10];
    const float* Wb      = (const float*)d_in[11];
    const float* bb      = (const float*)d_in[12];
    float* out = (float*)d_out;

    cudaFuncSetAttribute(cfc_kernel,
                         cudaFuncAttributeMaxDynamicSharedMemorySize, SMEM_BYTES);

    cfc_kernel<<<128, NTHRD, SMEM_BYTES>>>(
        x_codes, h0, tsp, W0, b0, W1, b1, W2, b2, Wa, ba, Wb, bb, out);
}

// round 12
// speedup vs baseline: 1.1788x; 1.0034x over previous
#include <cuda_runtime.h>

// CfC recurrent kernel, round 11: R9 cluster design (256 thr/CTA, weights
// SMEM-resident in a 4-CTA cluster) + GEMM2 weights pinned in REGISTERS
// (48 of 64 k-slices per thread; 16 remain in SMEM) to remove ~75% of the
// per-step weight crossbar traffic. B=256, S=2048, C=64, U=128, H=256.
// 32 clusters x 4 CTAs x 256 threads; cluster owns 8 batch rows end-to-end.
// Per-step f/h exchange via st.shared::cluster + 2 cluster barriers.
// All math packed fp32x2 FMA, row-pair lanes.

typedef unsigned long long u64;

#define S_LEN 2048
#define NTHRD 256
#define KREG 48                 // GEMM2 k-slices held in registers per thread

// SMEM layout (u64 units)
#define OW0   0                 // float[192][64]  = 6144 u64 (48KB)
#define OWH   6144              // float[256][128] = 16384 u64 (128KB)
#define OFEAT 22528             // u64 feat2[192][4]  (x|h as (row0,row1) pairs)
#define OFSM  23296             // u64 fsm2[256][4]   (backbone f pairs)
#define ORED  24320             // u64 red[2048]      (red1/red2 aliased)
#define OTOT  26368
#define SMEM_BYTES (OTOT * 8)   // 210944

__device__ __forceinline__ u64 pack2(float lo, float hi) {
    u64 r;
    asm("mov.b64 %0, {%1, %2};"
        : "=l"(r) : "r"(__float_as_uint(lo)), "r"(__float_as_uint(hi)));
    return r;
}
__device__ __forceinline__ void fma2(u64& d, u64 a, u64 b) {
    asm("fma.rn.f32x2 %0, %1, %2, %0;" : "+l"(d) : "l"(a), "l"(b));
}
__device__ __forceinline__ u64 add2(u64 a, u64 b) {
    u64 r;
    asm("add.rn.f32x2 %0, %1, %2;" : "=l"(r) : "l"(a), "l"(b));
    return r;
}
__device__ __forceinline__ float2 unpk(u64 v) {
    unsigned lo, hi;
    asm("mov.b64 {%0, %1}, %2;" : "=r"(lo), "=r"(hi) : "l"(v));
    return make_float2(__uint_as_float(lo), __uint_as_float(hi));
}
__device__ __forceinline__ unsigned smem_u32(const void* p) {
    unsigned a;
    asm("{ .reg .u64 t; cvta.to.shared.u64 t, %1; cvt.u32.u64 %0, t; }"
        : "=r"(a) : "l"(p));
    return a;
}
__device__ __forceinline__ unsigned mapa_rank(unsigned addr, unsigned rank) {
    unsigned r;
    asm("mapa.shared::cluster.u32 %0, %1, %2;" : "=r"(r) : "r"(addr), "r"(rank));
    return r;
}
__device__ __forceinline__ void st_cluster(unsigned addr, u64 v) {
    asm volatile("st.shared::cluster.b64 [%0], %1;" :: "r"(addr), "l"(v) : "memory");
}
__device__ __forceinline__ unsigned ctarank() {
    unsigned r;
    asm("mov.u32 %0, %%cluster_ctarank;" : "=r"(r));
    return r;
}
#define CLUSTER_BAR() do { \
    asm volatile("barrier.cluster.arrive.aligned;" ::: "memory"); \
    asm volatile("barrier.cluster.wait.aligned;"   ::: "memory"); \
} while (0)

__global__ void __launch_bounds__(NTHRD, 1) __cluster_dims__(4, 1, 1)
cfc_kernel(
    const float* __restrict__ x_codes,   // [B,S,64]
    const float* __restrict__ h0,        // [B,128]
    const float* __restrict__ tsp,       // [B,S]
    const float* __restrict__ W0,        // [192,256]
    const float* __restrict__ b0,        // [256]
    const float* __restrict__ W1, const float* __restrict__ b1,  // [256,128]
    const float* __restrict__ W2, const float* __restrict__ b2,
    const float* __restrict__ Wa, const float* __restrict__ ba,
    const float* __restrict__ Wb, const float* __restrict__ bb,
    float* __restrict__ out)             // [B,S,128]
{
    extern __shared__ u64 smu[];
    float* sW0  = (float*)(smu + OW0);
    float* sWH  = (float*)(smu + OWH);
    u64* feat2  = smu + OFEAT;
    u64* fsm2   = smu + OFSM;
    u64* red    = smu + ORED;

    const int tid = threadIdx.x;
    const unsigned rank = ctarank();
    const int brow = (blockIdx.x >> 2) * 8;

    // ---- one-time: load W0 slice [192][64] (cols 64*rank..) ----
    for (int idx = tid; idx < 192 * 16; idx += NTHRD) {     // float4 units
        int k = idx >> 4, q = idx & 15;
        float4 v = *(const float4*)(W0 + (size_t)k * 256 + rank * 64 + q * 4);
        ((float4*)sW0)[idx] = v;
    }
    // ---- one-time: head slice interleaved sWH[k][4j+h] = Wh[k][32*rank+j] ----
    for (int idx = tid; idx < 256 * 128; idx += NTHRD) {
        int k = idx >> 7, c = idx & 127, j = c >> 2, h = c & 3;
        const float* src = (h == 0 ? W1 : h == 1 ? W2 : h == 2 ? Wa : Wb);
        sWH[idx] = src[(size_t)k * 128 + 32 * rank + j];
    }
    // ---- one-time: h0 into feat2[64+u][rp] as (row2rp, row2rp+1) ----
    for (int idx = tid; idx < 512; idx += NTHRD) {
        int u = idx & 127, rp = idx >> 7;
        float a = h0[(size_t)(brow + 2 * rp) * 128 + u];
        float c = h0[(size_t)(brow + 2 * rp + 1) * 128 + u];
        feat2[(64 + u) * 4 + rp] = pack2(a, c);
    }
    __syncthreads();
    CLUSTER_BAR();

    // ---- DSMEM base addresses (once) ----
    unsigned fsm_base[4], feat_base[4];
    {
        unsigned lf = smem_u32(fsm2), lh = smem_u32(feat2);
        #pragma unroll
        for (int r = 0; r < 4; ++r) {
            fsm_base[r]  = mapa_rank(lf, (unsigned)r);
            feat_base[r] = mapa_rank(lh, (unsigned)r);
        }
    }

    // ---- per-thread role constants ----
    // GEMM1: 32 col-groups (2 cols) x 8 k-groups (24 k)
    const int cg  = tid & 31;
    const int k1b = (tid >> 5) * 24;
    // reduce1 / f-push: 64 cols x 4 row-pairs
    const int col1 = tid & 63;
    const int rp1  = tid >> 6;
    const int gc1  = 64 * (int)rank + col1;
    const u64 b0d  = pack2(b0[gc1], b0[gc1]);
    // GEMM2: 64 col-groups (2 of 128 local cols) x 4 k-groups (64 k)
    const int cg2 = tid & 63;
    const int k2b = (tid >> 6) * 64;
    const float* wp2c = sWH + k2b * 128 + 2 * cg2;
    const u64* fp2c = fsm2 + k2b * 4;
    // gate: 32 units x 4 row-pairs (threads 0..127)
    const int jg  = tid & 31;
    const int rpg = (tid >> 5) & 3;
    const int ug  = 32 * (int)rank + jg;
    const u64 b1d = pack2(b1[ug], b1[ug]);
    const u64 b2d = pack2(b2[ug], b2[ug]);
    const u64 bad = pack2(ba[ug], ba[ug]);
    const u64 bbd = pack2(bb[ug], bb[ug]);
    const int gr0 = brow + 2 * rpg;
    const float* tsa = tsp + (size_t)gr0 * S_LEN;
    const float* tsb = tsp + (size_t)(gr0 + 1) * S_LEN;
    float* outa = out + (size_t)gr0 * S_LEN * 128 + ug;
    float* outb = out + (size_t)(gr0 + 1) * S_LEN * 128 + ug;
    // x loader: 64 channels x 4 row-pairs
    const int ch  = tid & 63;
    const int rpx = tid >> 6;
    const float* xa = x_codes + (size_t)(brow + 2 * rpx) * S_LEN * 64 + ch;
    const float* xb = x_codes + (size_t)(brow + 2 * rpx + 1) * S_LEN * 64 + ch;

    // ---- pin first KREG GEMM2 weight k-slices in registers ----
    float2 wreg[KREG];
    #pragma unroll
    for (int k = 0; k < KREG; ++k)
        wreg[k] = *(const float2*)(wp2c + k * 128);

    float xr0 = xa[0], xr1 = xb[0];

    for (int s = 0; s < S_LEN; ++s) {
        // ts prefetch for gate (used far below)
        float tsv0 = 0.f, tsv1 = 0.f;
        if (tid < 128) { tsv0 = tsa[s]; tsv1 = tsb[s]; }

        // write x(s) (scaled) into feat2[0..63]
        feat2[ch * 4 + rpx] = pack2((xr0 - 65.0f) * 0.01f, (xr1 - 65.0f) * 0.01f);
        __syncthreads();  // S1: feat ready (x local, h via BAR_B of prev step)

        // ---- GEMM1 partials: 2 cols x 8 rows over 24 k ----
        u64 a00 = 0, a01 = 0, a02 = 0, a03 = 0;
        u64 a10 = 0, a11 = 0, a12 = 0, a13 = 0;
        {
            const float* wp = sW0 + k1b * 64 + 2 * cg;
            const u64* fp = feat2 + k1b * 4;
            #pragma unroll 12
            for (int k = 0; k < 24; ++k) {
                float2 w = *(const float2*)(wp + k * 64);
                u64 w0d = pack2(w.x, w.x), w1d = pack2(w.y, w.y);
                ulonglong2 f01 = *(const ulonglong2*)(fp + k * 4);
                ulonglong2 f23 = *(const ulonglong2*)(fp + k * 4 + 2);
                fma2(a00, f01.x, w0d); fma2(a01, f01.y, w0d);
                fma2(a02, f23.x, w0d); fma2(a03, f23.y, w0d);
                fma2(a10, f01.x, w1d); fma2(a11, f01.y, w1d);
                fma2(a12, f23.x, w1d); fma2(a13, f23.y, w1d);
            }
        }
        {   // red1 layout [ks(8)][rp(4)][col(64)]
            u64* rb = red + (tid >> 5) * 256 + 2 * cg;
            *(ulonglong2*)(rb)       = make_ulonglong2(a00, a10);
            *(ulonglong2*)(rb + 64)  = make_ulonglong2(a01, a11);
            *(ulonglong2*)(rb + 128) = make_ulonglong2(a02, a12);
            *(ulonglong2*)(rb + 192) = make_ulonglong2(a03, a13);
        }
        __syncthreads();  // S2: red1 ready

        // ---- reduce1 + lecun_tanh + push f slice to all 4 CTAs ----
        {
            const u64* rr = red + rp1 * 64 + col1;
            u64 ssum = rr[0];
            #pragma unroll
            for (int q = 1; q < 8; ++q) ssum = add2(ssum, rr[q * 256]);
            ssum = add2(ssum, b0d);
            float2 v = unpk(ssum);
            float t0 = 1.7159f * tanhf(0.666f * v.x);
            float t1 = 1.7159f * tanhf(0.666f * v.y);
            u64 fv = pack2(t0, t1);
            unsigned off = (unsigned)((gc1 * 4 + rp1) * 8);
            #pragma unroll
            for (int r = 0; r < 4; ++r) st_cluster(fsm_base[r] + off, fv);
        }
        // prefetch x(s+1) while waiting
        if (s + 1 < S_LEN) { xr0 = xa[(size_t)(s + 1) * 64]; xr1 = xb[(size_t)(s + 1) * 64]; }
        CLUSTER_BAR();  // BAR_A: all f slices delivered everywhere

        // ---- GEMM2 partials: 2 local cols x 8 rows over 64 k ----
        // First KREG k's use register-resident weights (no LDS for weights);
        // remaining k's stream weights from SMEM.
        u64 q00 = 0, q01 = 0, q02 = 0, q03 = 0;
        u64 q10 = 0, q11 = 0, q12 = 0, q13 = 0;
        #pragma unroll
        for (int k = 0; k < KREG; ++k) {
            float2 w = wreg[k];
            u64 w0d = pack2(w.x, w.x), w1d = pack2(w.y, w.y);
            ulonglong2 f01 = *(const ulonglong2*)(fp2c + k * 4);
            ulonglong2 f23 = *(const ulonglong2*)(fp2c + k * 4 + 2);
            fma2(q00, f01.x, w0d); fma2(q01, f01.y, w0d);
            fma2(q02, f23.x, w0d); fma2(q03, f23.y, w0d);
            fma2(q10, f01.x, w1d); fma2(q11, f01.y, w1d);
            fma2(q12, f23.x, w1d); fma2(q13, f23.y, w1d);
        }
        #pragma unroll 8
        for (int k = KREG; k < 64; ++k) {
            float2 w = *(const float2*)(wp2c + k * 128);
            u64 w0d = pack2(w.x, w.x), w1d = pack2(w.y, w.y);
            ulonglong2 f01 = *(const ulonglong2*)(fp2c + k * 4);
            ulonglong2 f23 = *(const ulonglong2*)(fp2c + k * 4 + 2);
            fma2(q00, f01.x, w0d); fma2(q01, f01.y, w0d);
            fma2(q02, f23.x, w0d); fma2(q03, f23.y, w0d);
            fma2(q10, f01.x, w1d); fma2(q11, f01.y, w1d);
            fma2(q12, f23.x, w1d); fma2(q13, f23.y, w1d);
        }
        {   // red2 layout [ks2(4)][rp(4)][col(128)] (aliases red1 — safe: BAR_A ordered)
            u64* rb = red + (tid >> 6) * 512 + 2 * cg2;
            *(ulonglong2*)(rb)       = make_ulonglong2(q00, q10);
            *(ulonglong2*)(rb + 128) = make_ulonglong2(q01, q11);
            *(ulonglong2*)(rb + 256) = make_ulonglong2(q02, q12);
            *(ulonglong2*)(rb + 384) = make_ulonglong2(q03, q13);
        }
        __syncthreads();  // S3: red2 ready

        // ---- gate: reduce 4 k-partials, sigmoid blend, out + h-push ----
        if (tid < 128) {
            const u64* rr = red + rpg * 128 + 4 * jg;
            ulonglong2 g0 = *(const ulonglong2*)(rr);       // (ff1, ff2) partial
            ulonglong2 g1 = *(const ulonglong2*)(rr + 2);   // (ta,  tb ) partial
            u64 p1 = g0.x, p2 = g0.y, pa = g1.x, pb = g1.y;
            #pragma unroll
            for (int q = 1; q < 4; ++q) {
                ulonglong2 h0v = *(const ulonglong2*)(rr + q * 512);
                ulonglong2 h1v = *(const ulonglong2*)(rr + q * 512 + 2);
                p1 = add2(p1, h0v.x); p2 = add2(p2, h0v.y);
                pa = add2(pa, h1v.x); pb = add2(pb, h1v.y);
            }
            p1 = add2(p1, b1d); p2 = add2(p2, b2d);
            pa = add2(pa, bad); pb = add2(pb, bbd);
            float2 f1v = unpk(p1), f2v = unpk(p2), av = unpk(pa), bv = unpk(pb);
            float z0 = bv.x - av.x * tsv0;
            float z1 = bv.y - av.y * tsv1;
            float ti0 = 1.0f / (1.0f + expf(-z0));
            float ti1 = 1.0f / (1.0f + expf(-z1));
            float nh0 = f1v.x + ti0 * (f2v.x - f1v.x);
            float nh1 = f1v.y + ti1 * (f2v.y - f1v.y);
            outa[(size_t)s * 128] = nh0;
            outb[(size_t)s * 128] = nh1;
            u64 hv = pack2(nh0, nh1);
            unsigned off = (unsigned)(((64 + ug) * 4 + rpg) * 8);
            #pragma unroll
            for (int r = 0; r < 4; ++r) st_cluster(feat_base[r] + off, hv);
        }
        CLUSTER_BAR();  // BAR_B: h delivered everywhere; safe to start next step
    }
}

extern "C" void kernel_launch(void* const* d_in, const int* in_sizes, int n_in,
                              void* d_out, int out_size) {
    const float* x_codes = (const float*)d_in[0];
    const float* h0      = (const float*)d_in[1];
    const float* tsp     = (const float*)d_in[2];
    const float* W0      = (const float*)d_in[3];
    const float* b0      = (const float*)d_in[4];
    const float* W1      = (const float*)d_in[5];
    const float* b1      = (const float*)d_in[6];
    const float* W2      = (const float*)d_in[7];
    const float* b2      = (const float*)d_in[8];
    const float* Wa      = (const float*)d_in[9];
    const float* ba      = (const float*)d_in[10];
    const float* Wb      = (const float*)d_in[11];
    const float* bb      = (const float*)d_in[12];
    float* out = (float*)d_out;

    cudaFuncSetAttribute(cfc_kernel,
                         cudaFuncAttributeMaxDynamicSharedMemorySize, SMEM_BYTES);

    cfc_kernel<<<128, NTHRD, SMEM_BYTES>>>(
        x_codes, h0, tsp, W0, b0, W1, b1, W2, b2, Wa, ba, Wb, bb, out);
}